// round 16
// baseline (speedup 1.0000x reference)
#include <cuda_runtime.h>
#include <cstdint>

static constexpr int NE   = 8;
static constexpr int HID  = 2048;
static constexpr int INTR = 8192;
static constexpr int TOK  = 1024;   // tokens per expert

// ---------------- scratch ----------------------------------------------------------
// X and h in swizzled A-fragment layout (block = 128m x 32k = 4096 floats per
// (e, m-strip, kt); float4 linear idx = ((mb*8+gq)*4+tg)*4+ks, stored at
// idx ^ ((idx>>3)&7) -- permutes within 128B lines only).
__device__ float g_xf[(size_t)NE * TOK * HID ];    //  64 MB
__device__ float g_h [(size_t)NE * TOK * INTR];    // 256 MB

// ---------------- PTX helpers ------------------------------------------------------
__device__ __forceinline__ uint32_t s2u(const void* p) {
    return (uint32_t)__cvta_generic_to_shared(p);
}
#define CP16(dst, src) \
    asm volatile("cp.async.cg.shared.global [%0], [%1], 16;" :: "r"(dst), "l"(src) : "memory")
#define CP_COMMIT() asm volatile("cp.async.commit_group;" ::: "memory")
#define CP_WAIT(n)  asm volatile("cp.async.wait_group %0;" :: "n"(n) : "memory")

__device__ __forceinline__ uint32_t f2tf(float f) {   // round-to-nearest tf32
    uint32_t r;
    asm("cvt.rna.tf32.f32 %0, %1;" : "=r"(r) : "f"(f));
    return r;
}
__device__ __forceinline__ float rtf(float f) { return __uint_as_float(f2tf(f)); }

__device__ __forceinline__ void mma8(float* c, const uint32_t* a, const uint32_t* b) {
    asm("mma.sync.aligned.m16n8k8.row.col.f32.tf32.tf32.f32 "
        "{%0,%1,%2,%3}, {%4,%5,%6,%7}, {%8,%9}, {%0,%1,%2,%3};"
        : "+f"(c[0]), "+f"(c[1]), "+f"(c[2]), "+f"(c[3])
        : "r"(a[0]), "r"(a[1]), "r"(a[2]), "r"(a[3]), "r"(b[0]), "r"(b[1]));
}
__device__ __forceinline__ float silu(float x) {
    return x * (1.0f / (1.0f + __expf(-x)));
}
__device__ __forceinline__ int swz(int idx) { return idx ^ ((idx >> 3) & 7); }

// ---------------- pass 0: X -> swizzled A-frag layout -------------------------------
__global__ void round_A_frag(const float* __restrict__ X, float* __restrict__ dst) {
    const int kt = blockIdx.x, ms = blockIdx.y, e = blockIdx.z;
    const int t = threadIdx.x;
    const float* s = X + ((size_t)(e * 8 + ms) * 128) * HID + kt * 32;
    float4* d = reinterpret_cast<float4*>(
        dst + (((size_t)(e * 8 + ms)) * 64 + kt) * 4096);
#pragma unroll
    for (int i = 0; i < 4; i++) {
        int dd = t + i * 256;
        int ks = dd & 3, tg = (dd >> 2) & 3, gq = (dd >> 4) & 7, mb = dd >> 7;
        int m = mb * 16 + gq, k = ks * 8 + tg;
        float4 o;
        o.x = rtf(s[(size_t)m * HID + k]);
        o.y = rtf(s[(size_t)(m + 8) * HID + k]);
        o.z = rtf(s[(size_t)m * HID + k + 4]);
        o.w = rtf(s[(size_t)(m + 8) * HID + k + 4]);
        d[swz(dd)] = o;
    }
}

// ---------------- GEMM geometry -----------------------------------------------------
// B gather bank = 8*tg + gq + const (strides == 8 mod 32): injective over the 32
// lanes -> conflict-free. Row byte-strides (288 / 544) are 16B-aligned for cp.async.
// gemm1: CTA 128m x 64n, warps 0-3 gate / 4-7 up, warp tile 64x32. 2 CTAs/SM.
static constexpr int G1_B_STRIDE = 72;                      // 64 + 8 pad
static constexpr int G1_B_F      = 32 * G1_B_STRIDE;        // 2304
static constexpr int G1_STAGE_F  = 4096 + 2 * G1_B_F;       // 8704
static constexpr int G1_STAGES   = 3;
static constexpr int G1_SMEM     = G1_STAGE_F * G1_STAGES * 4;  // 104448 B

// gemm2: CTA 128x128, warp 64x32 (2m x 4n). 2 CTAs/SM.
static constexpr int G2_B_STRIDE = 136;                     // 128 + 8 pad
static constexpr int G2_B_F      = 32 * G2_B_STRIDE;        // 4352
static constexpr int G2_STAGE_F  = 4096 + G2_B_F;           // 8448
static constexpr int G2_STAGES   = 3;
static constexpr int G2_SMEM     = G2_STAGE_F * G2_STAGES * 4;  // 101376 B

// ---------------- GEMM 1: h = up * silu(gate) ---------------------------------------
__global__ void __launch_bounds__(256, 2)
gemm_gateup(const float* __restrict__ Xf, const float* __restrict__ Wg,
            const float* __restrict__ Wu, float* __restrict__ Hf) {
    extern __shared__ float sm[];
    const int tid = threadIdx.x, wid = tid >> 5, lid = tid & 31;
    const int gq = lid >> 2, tg = lid & 3;
    const int half = wid >> 2;                 // 0 = gate, 1 = up
    const int w4 = wid & 3, wm = w4 & 1, wn = w4 >> 1;
    const int e = blockIdx.z, ms = blockIdx.x, ns = blockIdx.y;  // ns: 64-col strip
    const uint32_t sb = s2u(sm);

    const float* gA  = Xf + ((size_t)(e * 8 + ms) * 64) * 4096;     // + kt*4096
    const float* gBg = Wg + (size_t)e * HID * INTR + (size_t)ns * 64;
    const float* gBu = Wu + (size_t)e * HID * INTR + (size_t)ns * 64;

    float acc[4][4][4];
#pragma unroll
    for (int i = 0; i < 4; i++)
#pragma unroll
        for (int j = 0; j < 4; j++)
#pragma unroll
            for (int v = 0; v < 4; v++) acc[i][j][v] = 0.f;

    const int NT = HID / 32;   // 64

    // stage loader: A-frag 4 chunks/thread, Bg 2, Bu 2
#define G1_LOAD(slot, kt_)                                                          \
    {                                                                               \
        uint32_t base = sb + (uint32_t)((slot) * G1_STAGE_F) * 4;                   \
        const float* a_ = gA + (size_t)(kt_) * 4096;                                \
        _Pragma("unroll")                                                           \
        for (int i_ = 0; i_ < 4; i_++) {                                            \
            int idx_ = tid + i_ * 256;                                              \
            CP16(base + (uint32_t)idx_ * 16, a_ + (size_t)idx_ * 4);                \
        }                                                                           \
        _Pragma("unroll")                                                           \
        for (int i_ = 0; i_ < 2; i_++) {                                            \
            int idx_ = tid + i_ * 256;                                              \
            int r_ = idx_ >> 4, c_ = idx_ & 15;                                     \
            CP16(base + 16384 + (uint32_t)(r_ * G1_B_STRIDE + c_ * 4) * 4,          \
                 gBg + (size_t)((kt_) * 32 + r_) * INTR + c_ * 4);                  \
            CP16(base + 16384 + 4 * G1_B_F                                          \
                      + (uint32_t)(r_ * G1_B_STRIDE + c_ * 4) * 4,                  \
                 gBu + (size_t)((kt_) * 32 + r_) * INTR + c_ * 4);                  \
        }                                                                           \
    }

#pragma unroll
    for (int s = 0; s < G1_STAGES - 1; s++) {
        G1_LOAD(s, s);
        CP_COMMIT();
    }

    const int nb = wn * 32 + gq;    // base B column for this lane

    for (int kt = 0; kt < NT; kt++) {
        CP_WAIT(G1_STAGES - 2);
        __syncthreads();
        int pf = kt + G1_STAGES - 1;
        if (pf < NT) {
            G1_LOAD(pf % G1_STAGES, pf);
        }
        CP_COMMIT();

        const float4* As4 = reinterpret_cast<const float4*>(sm + (kt % G1_STAGES) * G1_STAGE_F);
        const float* Bs = sm + (kt % G1_STAGES) * G1_STAGE_F + 4096 + half * G1_B_F;

        // software pipeline: b[ks&1] consumed while b[(ks+1)&1] is gathered
        uint32_t b[2][4][2];
#pragma unroll
        for (int nt = 0; nt < 4; nt++) {
            b[0][nt][0] = f2tf(Bs[tg * G1_B_STRIDE + nt * 8 + nb]);
            b[0][nt][1] = f2tf(Bs[(tg + 4) * G1_B_STRIDE + nt * 8 + nb]);
        }
#pragma unroll
        for (int ks = 0; ks < 4; ks++) {
            float4 fa[4];
#pragma unroll
            for (int mt = 0; mt < 4; mt++) {
                int fi = (((wm * 4 + mt) * 8 + gq) * 4 + tg) * 4 + ks;
                fa[mt] = As4[swz(fi)];
            }
            if (ks < 3) {
                const int k1 = (ks + 1) * 8;
#pragma unroll
                for (int nt = 0; nt < 4; nt++) {
                    b[(ks + 1) & 1][nt][0] = f2tf(Bs[(k1 + tg) * G1_B_STRIDE + nt * 8 + nb]);
                    b[(ks + 1) & 1][nt][1] = f2tf(Bs[(k1 + tg + 4) * G1_B_STRIDE + nt * 8 + nb]);
                }
            }
#pragma unroll
            for (int mt = 0; mt < 4; mt++) {
                uint32_t a[4] = { __float_as_uint(fa[mt].x), __float_as_uint(fa[mt].y),
                                  __float_as_uint(fa[mt].z), __float_as_uint(fa[mt].w) };
#pragma unroll
                for (int nt = 0; nt < 4; nt++)
                    mma8(acc[mt][nt], a, b[ks & 1][nt]);
            }
        }
    }

    // ---- epilogue: stage silu(gate) and up in SMEM, emit h in swizzled frag order
    CP_WAIT(0);
    __syncthreads();
    float* sg = sm;             // 128 x 64
    float* su = sm + 8192;      // 128 x 64
    float* dst = half ? su : sg;
#pragma unroll
    for (int mt = 0; mt < 4; mt++)
#pragma unroll
        for (int nt = 0; nt < 4; nt++) {
            int row = wm * 64 + mt * 16 + gq;
            int col = wn * 32 + nt * 8 + tg * 2;
            float v0 = acc[mt][nt][0], v1 = acc[mt][nt][1];
            float v2 = acc[mt][nt][2], v3 = acc[mt][nt][3];
            if (half == 0) { v0 = silu(v0); v1 = silu(v1); v2 = silu(v2); v3 = silu(v3); }
            dst[row * 64 + col]           = v0;
            dst[row * 64 + col + 1]       = v1;
            dst[(row + 8) * 64 + col]     = v2;
            dst[(row + 8) * 64 + col + 1] = v3;
        }
    __syncthreads();

    // h frag blocks kt = ns*2 + b2 (each covers 32 cols)
    const size_t hbase = ((size_t)(e * 8 + ms) * 256 + (size_t)ns * 2) * 4096;
#pragma unroll
    for (int b2 = 0; b2 < 2; b2++) {
        float4* d = reinterpret_cast<float4*>(Hf + hbase + (size_t)b2 * 4096);
#pragma unroll
        for (int i = 0; i < 4; i++) {
            int dd = tid + i * 256;
            int ks = dd & 3, t2 = (dd >> 2) & 3, g2 = (dd >> 4) & 7, mb = dd >> 7;
            int m = mb * 16 + g2, c = b2 * 32 + ks * 8 + t2;
            float4 o;
            o.x = rtf(sg[m * 64 + c]           * su[m * 64 + c]);
            o.y = rtf(sg[(m + 8) * 64 + c]     * su[(m + 8) * 64 + c]);
            o.z = rtf(sg[m * 64 + c + 4]       * su[m * 64 + c + 4]);
            o.w = rtf(sg[(m + 8) * 64 + c + 4] * su[(m + 8) * 64 + c + 4]);
            d[swz(dd)] = o;
        }
    }
#undef G1_LOAD
}

// ---------------- GEMM 2: out = h @ down_w ------------------------------------------
__global__ void __launch_bounds__(256, 2)
gemm_down(const float* __restrict__ Hf, const float* __restrict__ Wd,
          float* __restrict__ Out) {
    extern __shared__ float sm[];
    const int tid = threadIdx.x, wid = tid >> 5, lid = tid & 31;
    const int gq = lid >> 2, tg = lid & 3;
    const int wm = wid >> 2, wn = wid & 3;          // 2 (m) x 4 (n)
    const int e = blockIdx.z, msb = blockIdx.x, ns = blockIdx.y;
    const uint32_t sb = s2u(sm);

    const float* gA = Hf + ((size_t)(e * 8 + msb) * 256) * 4096;    // + kt*4096
    const float* gB = Wd + (size_t)e * INTR * HID + (size_t)ns * 128;

    float acc[4][4][4];
#pragma unroll
    for (int i = 0; i < 4; i++)
#pragma unroll
        for (int j = 0; j < 4; j++)
#pragma unroll
            for (int v = 0; v < 4; v++) acc[i][j][v] = 0.f;

    const int NT = INTR / 32;   // 256

#define G2_LOAD(slot, kt_)                                                          \
    {                                                                               \
        uint32_t base = sb + (uint32_t)((slot) * G2_STAGE_F) * 4;                   \
        const float* a_ = gA + (size_t)(kt_) * 4096;                                \
        _Pragma("unroll")                                                           \
        for (int i_ = 0; i_ < 4; i_++) {                                            \
            int idx_ = tid + i_ * 256;                                              \
            CP16(base + (uint32_t)idx_ * 16, a_ + (size_t)idx_ * 4);                \
        }                                                                           \
        _Pragma("unroll")                                                           \
        for (int i_ = 0; i_ < 4; i_++) {                                            \
            int idx_ = tid + i_ * 256;                                              \
            int r_ = idx_ >> 5, c_ = idx_ & 31;                                     \
            CP16(base + 16384 + (uint32_t)(r_ * G2_B_STRIDE + c_ * 4) * 4,          \
                 gB + (size_t)((kt_) * 32 + r_) * HID + c_ * 4);                    \
        }                                                                           \
    }

#pragma unroll
    for (int s = 0; s < G2_STAGES - 1; s++) {
        G2_LOAD(s, s);
        CP_COMMIT();
    }

    const int nb = wn * 32 + gq;

    for (int kt = 0; kt < NT; kt++) {
        CP_WAIT(G2_STAGES - 2);
        __syncthreads();
        int pf = kt + G2_STAGES - 1;
        if (pf < NT) {
            G2_LOAD(pf % G2_STAGES, pf);
        }
        CP_COMMIT();

        const float4* As4 = reinterpret_cast<const float4*>(sm + (kt % G2_STAGES) * G2_STAGE_F);
        const float* Bs = sm + (kt % G2_STAGES) * G2_STAGE_F + 4096;

        uint32_t b[2][4][2];
#pragma unroll
        for (int nt = 0; nt < 4; nt++) {
            b[0][nt][0] = f2tf(Bs[tg * G2_B_STRIDE + nt * 8 + nb]);
            b[0][nt][1] = f2tf(Bs[(tg + 4) * G2_B_STRIDE + nt * 8 + nb]);
        }
#pragma unroll
        for (int ks = 0; ks < 4; ks++) {
            float4 fa[4];
#pragma unroll
            for (int mt = 0; mt < 4; mt++) {
                int fi = (((wm * 4 + mt) * 8 + gq) * 4 + tg) * 4 + ks;
                fa[mt] = As4[swz(fi)];
            }
            if (ks < 3) {
                const int k1 = (ks + 1) * 8;
#pragma unroll
                for (int nt = 0; nt < 4; nt++) {
                    b[(ks + 1) & 1][nt][0] = f2tf(Bs[(k1 + tg) * G2_B_STRIDE + nt * 8 + nb]);
                    b[(ks + 1) & 1][nt][1] = f2tf(Bs[(k1 + tg + 4) * G2_B_STRIDE + nt * 8 + nb]);
                }
            }
#pragma unroll
            for (int mt = 0; mt < 4; mt++) {
                uint32_t a[4] = { __float_as_uint(fa[mt].x), __float_as_uint(fa[mt].y),
                                  __float_as_uint(fa[mt].z), __float_as_uint(fa[mt].w) };
#pragma unroll
                for (int nt = 0; nt < 4; nt++)
                    mma8(acc[mt][nt], a, b[ks & 1][nt]);
            }
        }
    }

    const size_t ob = ((size_t)e * TOK + msb * 128 + wm * 64) * HID + ns * 128 + wn * 32;
#pragma unroll
    for (int mt = 0; mt < 4; mt++)
#pragma unroll
        for (int nt = 0; nt < 4; nt++) {
            int col = nt * 8 + tg * 2;
            int row = mt * 16 + gq;
            *reinterpret_cast<float2*>(&Out[ob + (size_t)row * HID + col]) =
                make_float2(acc[mt][nt][0], acc[mt][nt][1]);
            *reinterpret_cast<float2*>(&Out[ob + (size_t)(row + 8) * HID + col]) =
                make_float2(acc[mt][nt][2], acc[mt][nt][3]);
        }
#undef G2_LOAD
}

// ---------------- launch -------------------------------------------------------------
extern "C" void kernel_launch(void* const* d_in, const int* in_sizes, int n_in,
                              void* d_out, int out_size) {
    const float* X  = (const float*)d_in[0];
    const float* Wg = (const float*)d_in[1];
    const float* Wu = (const float*)d_in[2];
    const float* Wd = (const float*)d_in[3];
    float* out = (float*)d_out;

    float *xf, *hbuf;
    cudaGetSymbolAddress((void**)&xf,  g_xf);
    cudaGetSymbolAddress((void**)&hbuf, g_h);

    cudaFuncSetAttribute(gemm_gateup, cudaFuncAttributeMaxDynamicSharedMemorySize, G1_SMEM);
    cudaFuncSetAttribute(gemm_down,   cudaFuncAttributeMaxDynamicSharedMemorySize, G2_SMEM);

    // pass 0: X only (64 MB) -> swizzled A-frag layout
    round_A_frag<<<dim3(64, 8, 8), 256>>>(X, xf);

    // x = m tiles fastest -> consecutive CTAs share weight strips (L2 reuse)
    gemm_gateup<<<dim3(8, 128, 8), 256, G1_SMEM>>>(xf, Wg, Wu, hbuf);
    gemm_down  <<<dim3(8, 16, 8),  256, G2_SMEM>>>(hbuf, Wd, out);
}

// round 17
// speedup vs baseline: 1.0032x; 1.0032x over previous
#include <cuda_runtime.h>
#include <cstdint>

static constexpr int NE   = 8;
static constexpr int HID  = 2048;
static constexpr int INTR = 8192;
static constexpr int TOK  = 1024;   // tokens per expert

// ---------------- scratch ----------------------------------------------------------
// X and h in swizzled A-fragment layout (block = 128m x 32k = 4096 floats per
// (e, m-strip, kt); float4 linear idx = ((mb*8+gq)*4+tg)*4+ks, stored at
// idx ^ ((idx>>3)&7) -- permutes within 128B lines only).
__device__ float g_xf[(size_t)NE * TOK * HID ];    //  64 MB
__device__ float g_h [(size_t)NE * TOK * INTR];    // 256 MB

// ---------------- PTX helpers ------------------------------------------------------
__device__ __forceinline__ uint32_t s2u(const void* p) {
    return (uint32_t)__cvta_generic_to_shared(p);
}
#define CP16(dst, src) \
    asm volatile("cp.async.cg.shared.global [%0], [%1], 16;" :: "r"(dst), "l"(src) : "memory")
#define CP_COMMIT() asm volatile("cp.async.commit_group;" ::: "memory")
#define CP_WAIT(n)  asm volatile("cp.async.wait_group %0;" :: "n"(n) : "memory")

__device__ __forceinline__ uint32_t f2tf(float f) {   // round-to-nearest tf32
    uint32_t r;
    asm("cvt.rna.tf32.f32 %0, %1;" : "=r"(r) : "f"(f));
    return r;
}
__device__ __forceinline__ float rtf(float f) { return __uint_as_float(f2tf(f)); }

__device__ __forceinline__ void mma8(float* c, const uint32_t* a, const uint32_t* b) {
    asm("mma.sync.aligned.m16n8k8.row.col.f32.tf32.tf32.f32 "
        "{%0,%1,%2,%3}, {%4,%5,%6,%7}, {%8,%9}, {%0,%1,%2,%3};"
        : "+f"(c[0]), "+f"(c[1]), "+f"(c[2]), "+f"(c[3])
        : "r"(a[0]), "r"(a[1]), "r"(a[2]), "r"(a[3]), "r"(b[0]), "r"(b[1]));
}
__device__ __forceinline__ float silu(float x) {
    return x * (1.0f / (1.0f + __expf(-x)));
}
__device__ __forceinline__ int swz(int idx) { return idx ^ ((idx >> 3) & 7); }

// ---------------- pass 0: X -> swizzled A-frag layout -------------------------------
__global__ void round_A_frag(const float* __restrict__ X, float* __restrict__ dst) {
    const int kt = blockIdx.x, ms = blockIdx.y, e = blockIdx.z;
    const int t = threadIdx.x;
    const float* s = X + ((size_t)(e * 8 + ms) * 128) * HID + kt * 32;
    float4* d = reinterpret_cast<float4*>(
        dst + (((size_t)(e * 8 + ms)) * 64 + kt) * 4096);
#pragma unroll
    for (int i = 0; i < 4; i++) {
        int dd = t + i * 256;
        int ks = dd & 3, tg = (dd >> 2) & 3, gq = (dd >> 4) & 7, mb = dd >> 7;
        int m = mb * 16 + gq, k = ks * 8 + tg;
        float4 o;
        o.x = rtf(s[(size_t)m * HID + k]);
        o.y = rtf(s[(size_t)(m + 8) * HID + k]);
        o.z = rtf(s[(size_t)m * HID + k + 4]);
        o.w = rtf(s[(size_t)(m + 8) * HID + k + 4]);
        d[swz(dd)] = o;
    }
}

// ---------------- GEMM geometry -----------------------------------------------------
// B gather bank = 8*tg + gq + const (strides == 8 mod 32): injective over the 32
// lanes -> conflict-free. Row byte-strides (288 / 544) are 16B-aligned for cp.async.
// gemm1: CTA 128m x 64n, warps 0-3 gate / 4-7 up, warp tile 64x32. 2 CTAs/SM.
static constexpr int G1_B_STRIDE = 72;                      // 64 + 8 pad
static constexpr int G1_B_F      = 32 * G1_B_STRIDE;        // 2304
static constexpr int G1_STAGE_F  = 4096 + 2 * G1_B_F;       // 8704
static constexpr int G1_STAGES   = 3;
static constexpr int G1_SMEM     = G1_STAGE_F * G1_STAGES * 4;  // 104448 B

// gemm2: CTA 128x128, warp 64x32 (2m x 4n). 2 CTAs/SM.
static constexpr int G2_B_STRIDE = 136;                     // 128 + 8 pad
static constexpr int G2_B_F      = 32 * G2_B_STRIDE;        // 4352
static constexpr int G2_STAGE_F  = 4096 + G2_B_F;           // 8448
static constexpr int G2_STAGES   = 3;
static constexpr int G2_SMEM     = G2_STAGE_F * G2_STAGES * 4;  // 101376 B

// ---------------- GEMM 1: h = up * silu(gate) ---------------------------------------
__global__ void __launch_bounds__(256, 2)
gemm_gateup(const float* __restrict__ Xf, const float* __restrict__ Wg,
            const float* __restrict__ Wu, float* __restrict__ Hf) {
    extern __shared__ float sm[];
    const int tid = threadIdx.x, wid = tid >> 5, lid = tid & 31;
    const int gq = lid >> 2, tg = lid & 3;
    const int half = wid >> 2;                 // 0 = gate, 1 = up
    const int w4 = wid & 3, wm = w4 & 1, wn = w4 >> 1;
    const int e = blockIdx.z, ms = blockIdx.x, ns = blockIdx.y;  // ns: 64-col strip
    const uint32_t sb = s2u(sm);

    const float* gA  = Xf + ((size_t)(e * 8 + ms) * 64) * 4096;     // + kt*4096
    const float* gBg = Wg + (size_t)e * HID * INTR + (size_t)ns * 64;
    const float* gBu = Wu + (size_t)e * HID * INTR + (size_t)ns * 64;

    float acc[4][4][4];
#pragma unroll
    for (int i = 0; i < 4; i++)
#pragma unroll
        for (int j = 0; j < 4; j++)
#pragma unroll
            for (int v = 0; v < 4; v++) acc[i][j][v] = 0.f;

    const int NT = HID / 32;   // 64

    // stage loader: A-frag 4 chunks/thread, Bg 2, Bu 2
#define G1_LOAD(slot, kt_)                                                          \
    {                                                                               \
        uint32_t base = sb + (uint32_t)((slot) * G1_STAGE_F) * 4;                   \
        const float* a_ = gA + (size_t)(kt_) * 4096;                                \
        _Pragma("unroll")                                                           \
        for (int i_ = 0; i_ < 4; i_++) {                                            \
            int idx_ = tid + i_ * 256;                                              \
            CP16(base + (uint32_t)idx_ * 16, a_ + (size_t)idx_ * 4);                \
        }                                                                           \
        _Pragma("unroll")                                                           \
        for (int i_ = 0; i_ < 2; i_++) {                                            \
            int idx_ = tid + i_ * 256;                                              \
            int r_ = idx_ >> 4, c_ = idx_ & 15;                                     \
            CP16(base + 16384 + (uint32_t)(r_ * G1_B_STRIDE + c_ * 4) * 4,          \
                 gBg + (size_t)((kt_) * 32 + r_) * INTR + c_ * 4);                  \
            CP16(base + 16384 + 4 * G1_B_F                                          \
                      + (uint32_t)(r_ * G1_B_STRIDE + c_ * 4) * 4,                  \
                 gBu + (size_t)((kt_) * 32 + r_) * INTR + c_ * 4);                  \
        }                                                                           \
    }

#pragma unroll
    for (int s = 0; s < G1_STAGES - 1; s++) {
        G1_LOAD(s, s);
        CP_COMMIT();
    }

    const int nb = wn * 32 + gq;    // base B column for this lane

    for (int kt = 0; kt < NT; kt++) {
        CP_WAIT(G1_STAGES - 2);
        __syncthreads();
        int pf = kt + G1_STAGES - 1;
        if (pf < NT) {
            G1_LOAD(pf % G1_STAGES, pf);
        }
        CP_COMMIT();

        const float4* As4 = reinterpret_cast<const float4*>(sm + (kt % G1_STAGES) * G1_STAGE_F);
        const float* Bs = sm + (kt % G1_STAGES) * G1_STAGE_F + 4096 + half * G1_B_F;

        // software pipeline: b[ks&1] consumed while b[(ks+1)&1] is gathered
        uint32_t b[2][4][2];
#pragma unroll
        for (int nt = 0; nt < 4; nt++) {
            b[0][nt][0] = f2tf(Bs[tg * G1_B_STRIDE + nt * 8 + nb]);
            b[0][nt][1] = f2tf(Bs[(tg + 4) * G1_B_STRIDE + nt * 8 + nb]);
        }
#pragma unroll
        for (int ks = 0; ks < 4; ks++) {
            float4 fa[4];
#pragma unroll
            for (int mt = 0; mt < 4; mt++) {
                int fi = (((wm * 4 + mt) * 8 + gq) * 4 + tg) * 4 + ks;
                fa[mt] = As4[swz(fi)];
            }
            if (ks < 3) {
                const int k1 = (ks + 1) * 8;
#pragma unroll
                for (int nt = 0; nt < 4; nt++) {
                    b[(ks + 1) & 1][nt][0] = f2tf(Bs[(k1 + tg) * G1_B_STRIDE + nt * 8 + nb]);
                    b[(ks + 1) & 1][nt][1] = f2tf(Bs[(k1 + tg + 4) * G1_B_STRIDE + nt * 8 + nb]);
                }
            }
#pragma unroll
            for (int mt = 0; mt < 4; mt++) {
                uint32_t a[4] = { __float_as_uint(fa[mt].x), __float_as_uint(fa[mt].y),
                                  __float_as_uint(fa[mt].z), __float_as_uint(fa[mt].w) };
#pragma unroll
                for (int nt = 0; nt < 4; nt++)
                    mma8(acc[mt][nt], a, b[ks & 1][nt]);
            }
        }
    }

    // ---- epilogue: stage silu(gate) and up in SMEM, emit h in swizzled frag order
    CP_WAIT(0);
    __syncthreads();
    float* sg = sm;             // 128 x 64
    float* su = sm + 8192;      // 128 x 64
    float* dst = half ? su : sg;
#pragma unroll
    for (int mt = 0; mt < 4; mt++)
#pragma unroll
        for (int nt = 0; nt < 4; nt++) {
            int row = wm * 64 + mt * 16 + gq;
            int col = wn * 32 + nt * 8 + tg * 2;
            float v0 = acc[mt][nt][0], v1 = acc[mt][nt][1];
            float v2 = acc[mt][nt][2], v3 = acc[mt][nt][3];
            if (half == 0) { v0 = silu(v0); v1 = silu(v1); v2 = silu(v2); v3 = silu(v3); }
            dst[row * 64 + col]           = v0;
            dst[row * 64 + col + 1]       = v1;
            dst[(row + 8) * 64 + col]     = v2;
            dst[(row + 8) * 64 + col + 1] = v3;
        }
    __syncthreads();

    // h frag blocks kt = ns*2 + b2 (each covers 32 cols)
    const size_t hbase = ((size_t)(e * 8 + ms) * 256 + (size_t)ns * 2) * 4096;
#pragma unroll
    for (int b2 = 0; b2 < 2; b2++) {
        float4* d = reinterpret_cast<float4*>(Hf + hbase + (size_t)b2 * 4096);
#pragma unroll
        for (int i = 0; i < 4; i++) {
            int dd = tid + i * 256;
            int ks = dd & 3, t2 = (dd >> 2) & 3, g2 = (dd >> 4) & 7, mb = dd >> 7;
            int m = mb * 16 + g2, c = b2 * 32 + ks * 8 + t2;
            float4 o;
            o.x = rtf(sg[m * 64 + c]           * su[m * 64 + c]);
            o.y = rtf(sg[(m + 8) * 64 + c]     * su[(m + 8) * 64 + c]);
            o.z = rtf(sg[m * 64 + c + 4]       * su[m * 64 + c + 4]);
            o.w = rtf(sg[(m + 8) * 64 + c + 4] * su[(m + 8) * 64 + c + 4]);
            d[swz(dd)] = o;
        }
    }
#undef G1_LOAD
}

// ---------------- GEMM 2: out = h @ down_w ------------------------------------------
__global__ void __launch_bounds__(256, 2)
gemm_down(const float* __restrict__ Hf, const float* __restrict__ Wd,
          float* __restrict__ Out) {
    extern __shared__ float sm[];
    const int tid = threadIdx.x, wid = tid >> 5, lid = tid & 31;
    const int gq = lid >> 2, tg = lid & 3;
    const int wm = wid >> 2, wn = wid & 3;          // 2 (m) x 4 (n)
    const int e = blockIdx.z, msb = blockIdx.x, ns = blockIdx.y;
    const uint32_t sb = s2u(sm);

    const float* gA = Hf + ((size_t)(e * 8 + msb) * 256) * 4096;    // + kt*4096
    const float* gB = Wd + (size_t)e * INTR * HID + (size_t)ns * 128;

    float acc[4][4][4];
#pragma unroll
    for (int i = 0; i < 4; i++)
#pragma unroll
        for (int j = 0; j < 4; j++)
#pragma unroll
            for (int v = 0; v < 4; v++) acc[i][j][v] = 0.f;

    const int NT = INTR / 32;   // 256

#define G2_LOAD(slot, kt_)                                                          \
    {                                                                               \
        uint32_t base = sb + (uint32_t)((slot) * G2_STAGE_F) * 4;                   \
        const float* a_ = gA + (size_t)(kt_) * 4096;                                \
        _Pragma("unroll")                                                           \
        for (int i_ = 0; i_ < 4; i_++) {                                            \
            int idx_ = tid + i_ * 256;                                              \
            CP16(base + (uint32_t)idx_ * 16, a_ + (size_t)idx_ * 4);                \
        }                                                                           \
        _Pragma("unroll")                                                           \
        for (int i_ = 0; i_ < 4; i_++) {                                            \
            int idx_ = tid + i_ * 256;                                              \
            int r_ = idx_ >> 5, c_ = idx_ & 31;                                     \
            CP16(base + 16384 + (uint32_t)(r_ * G2_B_STRIDE + c_ * 4) * 4,          \
                 gB + (size_t)((kt_) * 32 + r_) * HID + c_ * 4);                    \
        }                                                                           \
    }

#pragma unroll
    for (int s = 0; s < G2_STAGES - 1; s++) {
        G2_LOAD(s, s);
        CP_COMMIT();
    }

    const int nb = wn * 32 + gq;

    for (int kt = 0; kt < NT; kt++) {
        CP_WAIT(G2_STAGES - 2);
        __syncthreads();
        int pf = kt + G2_STAGES - 1;
        if (pf < NT) {
            G2_LOAD(pf % G2_STAGES, pf);
        }
        CP_COMMIT();

        const float4* As4 = reinterpret_cast<const float4*>(sm + (kt % G2_STAGES) * G2_STAGE_F);
        const float* Bs = sm + (kt % G2_STAGES) * G2_STAGE_F + 4096;

        uint32_t b[2][4][2];
#pragma unroll
        for (int nt = 0; nt < 4; nt++) {
            b[0][nt][0] = f2tf(Bs[tg * G2_B_STRIDE + nt * 8 + nb]);
            b[0][nt][1] = f2tf(Bs[(tg + 4) * G2_B_STRIDE + nt * 8 + nb]);
        }
#pragma unroll
        for (int ks = 0; ks < 4; ks++) {
            float4 fa[4];
#pragma unroll
            for (int mt = 0; mt < 4; mt++) {
                int fi = (((wm * 4 + mt) * 8 + gq) * 4 + tg) * 4 + ks;
                fa[mt] = As4[swz(fi)];
            }
            if (ks < 3) {
                const int k1 = (ks + 1) * 8;
#pragma unroll
                for (int nt = 0; nt < 4; nt++) {
                    b[(ks + 1) & 1][nt][0] = f2tf(Bs[(k1 + tg) * G2_B_STRIDE + nt * 8 + nb]);
                    b[(ks + 1) & 1][nt][1] = f2tf(Bs[(k1 + tg + 4) * G2_B_STRIDE + nt * 8 + nb]);
                }
            }
#pragma unroll
            for (int mt = 0; mt < 4; mt++) {
                uint32_t a[4] = { __float_as_uint(fa[mt].x), __float_as_uint(fa[mt].y),
                                  __float_as_uint(fa[mt].z), __float_as_uint(fa[mt].w) };
#pragma unroll
                for (int nt = 0; nt < 4; nt++)
                    mma8(acc[mt][nt], a, b[ks & 1][nt]);
            }
        }
    }

    const size_t ob = ((size_t)e * TOK + msb * 128 + wm * 64) * HID + ns * 128 + wn * 32;
#pragma unroll
    for (int mt = 0; mt < 4; mt++)
#pragma unroll
        for (int nt = 0; nt < 4; nt++) {
            int col = nt * 8 + tg * 2;
            int row = mt * 16 + gq;
            *reinterpret_cast<float2*>(&Out[ob + (size_t)row * HID + col]) =
                make_float2(acc[mt][nt][0], acc[mt][nt][1]);
            *reinterpret_cast<float2*>(&Out[ob + (size_t)(row + 8) * HID + col]) =
                make_float2(acc[mt][nt][2], acc[mt][nt][3]);
        }
#undef G2_LOAD
}

// ---------------- launch -------------------------------------------------------------
extern "C" void kernel_launch(void* const* d_in, const int* in_sizes, int n_in,
                              void* d_out, int out_size) {
    const float* X  = (const float*)d_in[0];
    const float* Wg = (const float*)d_in[1];
    const float* Wu = (const float*)d_in[2];
    const float* Wd = (const float*)d_in[3];
    float* out = (float*)d_out;

    float *xf, *hbuf;
    cudaGetSymbolAddress((void**)&xf,  g_xf);
    cudaGetSymbolAddress((void**)&hbuf, g_h);

    cudaFuncSetAttribute(gemm_gateup, cudaFuncAttributeMaxDynamicSharedMemorySize, G1_SMEM);
    cudaFuncSetAttribute(gemm_down,   cudaFuncAttributeMaxDynamicSharedMemorySize, G2_SMEM);

    // pass 0: X only (64 MB) -> swizzled A-frag layout
    round_A_frag<<<dim3(64, 8, 8), 256>>>(X, xf);

    // x = m tiles fastest -> consecutive CTAs share weight strips (L2 reuse)
    gemm_gateup<<<dim3(8, 128, 8), 256, G1_SMEM>>>(xf, Wg, Wu, hbuf);
    gemm_down  <<<dim3(8, 16, 8),  256, G2_SMEM>>>(hbuf, Wd, out);
}